// round 7
// baseline (speedup 1.0000x reference)
#include <cuda_runtime.h>
#include <cuda_bf16.h>

// NLL closed form for V = sig2e*I + sig2b*Z Z^T (block-diagonal per group):
//   logdet V   = N*log(sig2e) + sum_{g:n_g>0} [log(sig2e + n_g*sig2b) - log(sig2e)]
//   r^T V^-1 r = (1/sig2e) * [ sum r_i^2 - sum_g sig2b*s_g^2/(sig2e+n_g*sig2b) ]
//
// Fused single kernel, 2 CTAs x 1024 threads x 2 elems. One packed 64-bit
// REDG per element into an L2-resident histogram (count bits[46:64), biased
// fixed-point sum bits[0:46): u = round(r*2^26)+2^32 > 0, group sum < 2^45,
// no carry into count). bar.sync + ONE acq_rel ticket atomic per CTA; the
// winner (2nd of 2 -> minimal fan-in) decodes all 1000 bins in one L2 round,
// with the g_ss_fx load + scratch resets hoisted OFF the serial tail so they
// overlap the bin math. Float shuffle-tree reduce, write, done.

#define N_ELEMS    4096
#define NUM_GROUPS 1000
#define LOG_2PI    1.8378770664093453
#define NCTAS      2
#define NTHREADS   1024
#define ELEMS_PER_THREAD 2

#define FX_SCALE   67108864.0f            // 2^26
#define FX_INV_F   (1.0f / 67108864.0f)
#define FX_INV_D   (1.0 / 67108864.0)
#define SUM_BITS   46
#define MASK46     ((1ULL << SUM_BITS) - 1ULL)
#define CNT_ONE    (1ULL << SUM_BITS)
#define BIAS       (1LL << 32)

// Persistent scratch (zero at module load; winner re-zeroes each launch).
__device__ unsigned long long g_hist[NUM_GROUPS];
__device__ unsigned long long g_ss_fx;
__device__ unsigned int       g_done;

__global__ __launch_bounds__(NTHREADS, 1)
void nll_fused_kernel(const float* __restrict__ y_true,
                      const float* __restrict__ y_pred,
                      const int*   __restrict__ z_idx,
                      const float* __restrict__ p_sig2e,
                      const float* __restrict__ p_sig2b,
                      float* __restrict__ out)
{
    __shared__ float s_red[2][32];
    __shared__ unsigned long long s_ss;
    __shared__ int s_last;

    const int tid  = threadIdx.x;
    const int lane = tid & 31;
    const int wid  = tid >> 5;
    const int base = blockIdx.x * (NTHREADS * ELEMS_PER_THREAD) + tid;

    // hoisted scalar loads: overlap the element pass
    const float sig2e = __ldg(p_sig2e);
    const float sig2b = __ldg(p_sig2b);

    // ---- element pass: one packed REDG per element, 2 elems/thread ----
    float ss = 0.0f;
    #pragma unroll
    for (int k = 0; k < ELEMS_PER_THREAD; k++) {
        int   i = base + k * NTHREADS;
        float r = y_true[i] - y_pred[i];
        int   g = z_idx[i];
        g = (g < 0) ? 0 : (g >= NUM_GROUPS ? NUM_GROUPS - 1 : g);
        long long u = llrintf(r * FX_SCALE) + BIAS;   // in (0, 2^33)
        atomicAdd(&g_hist[g], CNT_ONE + (unsigned long long)u);
        ss += r * r;
    }

    // sum of squares: warp shuffle + one integer RED per warp (deterministic)
    #pragma unroll
    for (int off = 16; off > 0; off >>= 1)
        ss += __shfl_down_sync(0xFFFFFFFFu, ss, off);
    if (lane == 0)
        atomicAdd(&g_ss_fx, (unsigned long long)llrintf(ss * FX_SCALE));

    // ---- ticket: bar.sync orders all CTA writes before tid0's release;
    //      the winner's acquire makes the peer CTA's REDGs visible ----
    __syncthreads();
    if (tid == 0) {
        unsigned int old;
        asm volatile("atom.acq_rel.gpu.global.add.u32 %0, [%1], %2;"
                     : "=r"(old)
                     : "l"(&g_done), "r"(1u)
                     : "memory");
        s_last = (old == NCTAS - 1);
    }
    __syncthreads();
    if (!s_last) return;

    // ---- finish (winner CTA): hoist ss load + resets off the tail ----
    if (tid == 0) {
        s_ss    = g_ss_fx;     // issues now; latency overlaps bin decode
        g_ss_fx = 0ULL;
        g_done  = 0u;
    }

    const float log_sig2e = __logf(sig2e);

    float v1 = 0.0f;   // sum_g [log(sig2e + n_g sig2b) - log(sig2e)]
    float v2 = 0.0f;   // sum_g sig2b * s_g^2 / (sig2e + n_g sig2b)

    if (tid < NUM_GROUPS) {
        unsigned long long h = g_hist[tid];
        g_hist[tid] = 0ULL;                         // restore for next replay
        int       n    = (int)(h >> SUM_BITS);
        long long s_fx = (long long)(h & MASK46) - (long long)n * BIAS;
        if (n > 0) {
            float d = sig2e + (float)n * sig2b;
            float s = __ll2float_rn(s_fx) * FX_INV_F;
            v1 = __logf(d) - log_sig2e;
            v2 = __fdividef(sig2b * s * s, d);
        }
    }

    // float block reduction: 32 warps -> smem -> warp 0
    #pragma unroll
    for (int off = 16; off > 0; off >>= 1) {
        v1 += __shfl_down_sync(0xFFFFFFFFu, v1, off);
        v2 += __shfl_down_sync(0xFFFFFFFFu, v2, off);
    }
    if (lane == 0) { s_red[0][wid] = v1; s_red[1][wid] = v2; }
    __syncthreads();
    if (wid == 0) {
        v1 = s_red[0][lane];
        v2 = s_red[1][lane];
        #pragma unroll
        for (int off = 16; off > 0; off >>= 1) {
            v1 += __shfl_down_sync(0xFFFFFFFFu, v1, off);
            v2 += __shfl_down_sync(0xFFFFFFFFu, v2, off);
        }
        if (lane == 0) {
            double ss_tot = (double)s_ss * FX_INV_D;   // smem, already resident
            double logdet = (double)N_ELEMS * (double)log_sig2e + (double)v1;
            double quad   = (ss_tot - (double)v2) / (double)sig2e;
            double total  = 0.5 * (double)N_ELEMS * LOG_2PI
                          + 0.5 * logdet
                          + 0.5 * quad;
            out[0] = (float)total;
        }
    }
}

extern "C" void kernel_launch(void* const* d_in, const int* in_sizes, int n_in,
                              void* d_out, int out_size)
{
    const float* y_true = (const float*)d_in[0];
    const float* y_pred = (const float*)d_in[1];
    const int*   z_idx  = (const int*)d_in[2];
    const float* sig2e  = (const float*)d_in[3];
    const float* sig2b  = (const float*)d_in[4];
    float*       out    = (float*)d_out;

    nll_fused_kernel<<<NCTAS, NTHREADS>>>(y_true, y_pred, z_idx, sig2e, sig2b, out);
}

// round 8
// speedup vs baseline: 1.0072x; 1.0072x over previous
#include <cuda_runtime.h>
#include <cuda_bf16.h>

// NLL closed form for V = sig2e*I + sig2b*Z Z^T (block-diagonal per group):
//   logdet V   = N*log(sig2e) + sum_{g:n_g>0} [log(sig2e + n_g*sig2b) - log(sig2e)]
//   r^T V^-1 r = (1/sig2e) * [ sum r_i^2 - sum_g sig2b*s_g^2/(sig2e+n_g*sig2b) ]
//
// Fused single kernel, 4 CTAs x 1024 threads, 1 elem/thread (best-measured
// config: shortest per-CTA critical path; R7 showed 2 CTAs x 2 elems is
// worse). One packed 64-bit REDG per element into the L2-resident histogram
// (count bits[46:64), biased fixed-point sum bits[0:46):
// u = round(r*2^26)+2^32 > 0, group sum < 2^45 -> no carry into count).
// bar.sync + ONE acq_rel ticket atomic per CTA; the winner decodes all 1000
// bins in one L2 round. Tail hoists: g_ss_fx load -> smem and scratch resets
// issue right after the ticket (overlap bin decode); log(sig2e) computed
// BEFORE the ticket (depends only on pre-hoisted scalars).

#define N_ELEMS    4096
#define NUM_GROUPS 1000
#define LOG_2PI    1.8378770664093453
#define NCTAS      4
#define NTHREADS   1024

#define FX_SCALE   67108864.0f            // 2^26
#define FX_INV_F   (1.0f / 67108864.0f)
#define FX_INV_D   (1.0 / 67108864.0)
#define SUM_BITS   46
#define MASK46     ((1ULL << SUM_BITS) - 1ULL)
#define CNT_ONE    (1ULL << SUM_BITS)
#define BIAS       (1LL << 32)

// Persistent scratch (zero at module load; winner re-zeroes each launch).
__device__ unsigned long long g_hist[NUM_GROUPS];
__device__ unsigned long long g_ss_fx;
__device__ unsigned int       g_done;

__global__ __launch_bounds__(NTHREADS, 1)
void nll_fused_kernel(const float* __restrict__ y_true,
                      const float* __restrict__ y_pred,
                      const int*   __restrict__ z_idx,
                      const float* __restrict__ p_sig2e,
                      const float* __restrict__ p_sig2b,
                      float* __restrict__ out)
{
    __shared__ float s_red[2][32];
    __shared__ unsigned long long s_ss;
    __shared__ int s_last;

    const int tid  = threadIdx.x;
    const int lane = tid & 31;
    const int wid  = tid >> 5;
    const int i    = blockIdx.x * NTHREADS + tid;

    // hoisted scalar loads + log: overlap the element pass, off the tail
    const float sig2e = __ldg(p_sig2e);
    const float sig2b = __ldg(p_sig2b);
    const float log_sig2e = __logf(sig2e);

    // ---- element pass: one packed REDG per element ----
    float r = y_true[i] - y_pred[i];
    int   g = z_idx[i];
    g = (g < 0) ? 0 : (g >= NUM_GROUPS ? NUM_GROUPS - 1 : g);

    long long u = llrintf(r * FX_SCALE) + BIAS;     // in (0, 2^33)
    atomicAdd(&g_hist[g], CNT_ONE + (unsigned long long)u);

    // sum of squares: warp shuffle + one integer RED per warp (deterministic)
    float ss = r * r;
    #pragma unroll
    for (int off = 16; off > 0; off >>= 1)
        ss += __shfl_down_sync(0xFFFFFFFFu, ss, off);
    if (lane == 0)
        atomicAdd(&g_ss_fx, (unsigned long long)llrintf(ss * FX_SCALE));

    // ---- ticket: bar.sync orders all CTA writes before tid0's release;
    //      the winner's acquire makes all peers' REDGs visible ----
    __syncthreads();
    if (tid == 0) {
        unsigned int old;
        asm volatile("atom.acq_rel.gpu.global.add.u32 %0, [%1], %2;"
                     : "=r"(old)
                     : "l"(&g_done), "r"(1u)
                     : "memory");
        s_last = (old == NCTAS - 1);
    }
    __syncthreads();
    if (!s_last) return;

    // ---- finish (winner CTA): ss load + resets issue first, overlap decode
    if (tid == 0) {
        s_ss    = g_ss_fx;     // latency hidden behind bin decode below
        g_ss_fx = 0ULL;
        g_done  = 0u;
    }

    float v1 = 0.0f;   // sum_g [log(sig2e + n_g sig2b) - log(sig2e)]
    float v2 = 0.0f;   // sum_g sig2b * s_g^2 / (sig2e + n_g sig2b)

    if (tid < NUM_GROUPS) {
        unsigned long long h = g_hist[tid];
        g_hist[tid] = 0ULL;                         // restore for next replay
        int       n    = (int)(h >> SUM_BITS);
        long long s_fx = (long long)(h & MASK46) - (long long)n * BIAS;
        if (n > 0) {
            float d = sig2e + (float)n * sig2b;
            float s = __ll2float_rn(s_fx) * FX_INV_F;
            v1 = __logf(d) - log_sig2e;
            v2 = __fdividef(sig2b * s * s, d);
        }
    }

    // float block reduction: 32 warps -> smem -> warp 0
    #pragma unroll
    for (int off = 16; off > 0; off >>= 1) {
        v1 += __shfl_down_sync(0xFFFFFFFFu, v1, off);
        v2 += __shfl_down_sync(0xFFFFFFFFu, v2, off);
    }
    if (lane == 0) { s_red[0][wid] = v1; s_red[1][wid] = v2; }
    __syncthreads();
    if (wid == 0) {
        v1 = s_red[0][lane];
        v2 = s_red[1][lane];
        #pragma unroll
        for (int off = 16; off > 0; off >>= 1) {
            v1 += __shfl_down_sync(0xFFFFFFFFu, v1, off);
            v2 += __shfl_down_sync(0xFFFFFFFFu, v2, off);
        }
        if (lane == 0) {
            double ss_tot = (double)s_ss * FX_INV_D;   // smem, already resident
            double logdet = (double)N_ELEMS * (double)log_sig2e + (double)v1;
            double quad   = (ss_tot - (double)v2) / (double)sig2e;
            double total  = 0.5 * (double)N_ELEMS * LOG_2PI
                          + 0.5 * logdet
                          + 0.5 * quad;
            out[0] = (float)total;
        }
    }
}

extern "C" void kernel_launch(void* const* d_in, const int* in_sizes, int n_in,
                              void* d_out, int out_size)
{
    const float* y_true = (const float*)d_in[0];
    const float* y_pred = (const float*)d_in[1];
    const int*   z_idx  = (const int*)d_in[2];
    const float* sig2e  = (const float*)d_in[3];
    const float* sig2b  = (const float*)d_in[4];
    float*       out    = (float*)d_out;

    nll_fused_kernel<<<NCTAS, NTHREADS>>>(y_true, y_pred, z_idx, sig2e, sig2b, out);
}